// round 14
// baseline (speedup 1.0000x reference)
#include <cuda_runtime.h>
#include <cuda_fp16.h>
#include <math.h>
#include <stdint.h>

// Problem constants
#define D      512
#define NNODES 20000
#define NEDGES 100000
#define EPRIME (NEDGES + NNODES)
#define H1v    8
#define C1v    64
#define H2v    4
#define C2v    128
#define CHUNK  128

// ---------------- scratch (device globals; no allocation allowed) -------------
__device__ float g_xp[(size_t)NNODES * D];
__device__ float g_asrc[(size_t)NNODES * H1v];
__device__ float g_adst[(size_t)NNODES * H1v];
__device__ int   g_deg[NNODES];
__device__ int   g_rowstart[NNODES];
__device__ int   g_cursor[NNODES];
__device__ int   g_csr[EPRIME];
__device__ float g_accum[2];
__device__ int   g_mask_byte;
__device__ int   g_total;
__device__ unsigned g_bar;      // mega-kernel barrier (monotonic, reset at exit)
__device__ unsigned g_exit;     // mega-kernel exit counter
__device__ unsigned g_done;     // agg2 completion counter
__device__ __half g_Ahi[(size_t)NNODES * D];
__device__ __half g_Alo[(size_t)NNODES * D];
__device__ __half g_Bhi[(size_t)D * D];
__device__ __half g_B2hi[(size_t)D * D];

// ---------------- helpers ----------------------------------------------------
__device__ __forceinline__ float warp_max(float v) {
    #pragma unroll
    for (int o = 16; o; o >>= 1) v = fmaxf(v, __shfl_xor_sync(0xffffffffu, v, o));
    return v;
}
__device__ __forceinline__ float warp_sum(float v) {
    #pragma unroll
    for (int o = 16; o; o >>= 1) v += __shfl_xor_sync(0xffffffffu, v, o);
    return v;
}

__device__ __forceinline__ void mma16816(float* c, const uint32_t* a, const uint32_t* b) {
    asm volatile(
        "mma.sync.aligned.m16n8k16.row.col.f32.f16.f16.f32 "
        "{%0,%1,%2,%3}, {%4,%5,%6,%7}, {%8,%9}, {%0,%1,%2,%3};\n"
        : "+f"(c[0]), "+f"(c[1]), "+f"(c[2]), "+f"(c[3])
        : "r"(a[0]), "r"(a[1]), "r"(a[2]), "r"(a[3]), "r"(b[0]), "r"(b[1]));
}
__device__ __forceinline__ void ldsm4(uint32_t* r, uint32_t addr) {
    asm volatile("ldmatrix.sync.aligned.m8n8.x4.shared.b16 {%0,%1,%2,%3}, [%4];\n"
        : "=r"(r[0]), "=r"(r[1]), "=r"(r[2]), "=r"(r[3]) : "r"(addr));
}
__device__ __forceinline__ void ldsm4t(uint32_t* r, uint32_t addr) {
    asm volatile("ldmatrix.sync.aligned.m8n8.x4.trans.shared.b16 {%0,%1,%2,%3}, [%4];\n"
        : "=r"(r[0]), "=r"(r[1]), "=r"(r[2]), "=r"(r[3]) : "r"(addr));
}
__device__ __forceinline__ void cpasync16(uint32_t dst, const void* src, int srcsize) {
    asm volatile("cp.async.cg.shared.global [%0], [%1], 16, %2;\n"
        :: "r"(dst), "l"(src), "r"(srcsize));
}
__device__ __forceinline__ void cp_commit() { asm volatile("cp.async.commit_group;\n"); }
template<int NW> __device__ __forceinline__ void cp_wait() {
    asm volatile("cp.async.wait_group %0;\n" :: "n"(NW));
}

// ---------------- mega kernel: init + W splits + CSR build (grid-synced) -------
__device__ __forceinline__ void grid_sync_phase(unsigned target) {
    __syncthreads();
    if (threadIdx.x == 0) {
        __threadfence();
        atomicAdd(&g_bar, 1u);
        while (atomicAdd(&g_bar, 0u) < target) { }
        __threadfence();
    }
    __syncthreads();
}

__global__ __launch_bounds__(256)
void mega_kernel(const int* __restrict__ ei, const unsigned int* __restrict__ m,
                 const float* __restrict__ W1, const float* __restrict__ W2,
                 __half* __restrict__ B1hi, __half* __restrict__ B2hi,
                 int E, int N) {
    const unsigned nb = gridDim.x;
    int gi = blockIdx.x * blockDim.x + threadIdx.x;
    int stride = nb * blockDim.x;
    const int nw = D * D;
    // ---- phase 0: zero state + split W1/W2 to fp16 ----
    if (gi < N) g_deg[gi] = 0;
    if (gi == 0) {
        g_accum[0] = 0.f; g_accum[1] = 0.f;
        g_total = 0; g_mask_byte = 0; g_done = 0u;
    }
    for (int i = gi; i < 2 * nw; i += stride) {
        if (i < nw) B1hi[i] = __float2half_rn(W1[i]);
        else        B2hi[i - nw] = __float2half_rn(W2[i - nw]);
    }
    grid_sync_phase(nb);
    // ---- phase 1: histogram + mask dtype detect ----
    if (gi < N / 4) {
        unsigned v = m[gi];
        if (v != 0u && v != 1u && v != 0x3F800000u) atomicOr(&g_mask_byte, 1);
    }
    if (gi < E + N) {
        int d = (gi < E) ? ei[E + gi] : (gi - E);
        atomicAdd(&g_deg[d], 1);
    }
    grid_sync_phase(2 * nb);
    // ---- phase 2: segment offsets ----
    if (gi < N) {
        int base = atomicAdd(&g_total, g_deg[gi]);
        g_rowstart[gi] = base;
        g_cursor[gi] = base;
    }
    grid_sync_phase(3 * nb);
    // ---- phase 3: scatter ----
    if (gi < E + N) {
        int d = (gi < E) ? ei[E + gi] : (gi - E);
        int pos = atomicAdd(&g_cursor[d], 1);
        g_csr[pos] = gi;
    }
    // ---- exit: last block resets barrier state for next graph replay ----
    __syncthreads();
    if (threadIdx.x == 0) {
        __threadfence();
        if (atomicAdd(&g_exit, 1u) == nb - 1) {
            atomicExch(&g_bar, 0u);
            atomicExch(&g_exit, 0u);
        }
    }
}

// ---------------- tensor-core GEMM + fused attention (atomic-free) --------------
// A either fp16 hi/lo (A32==null) or fp32 (A32!=null, converted in-smem).
#define LDA_S 40
#define LDB_S 136
#define ST_A32 0                                   // 128 x 36 floats = 18432 B
#define ST_AHI 18432                               // 128 x 40 halves = 10240 B
#define ST_ALO 28672                               // 10240 B
#define ST_B   38912                               // 32 x 136 halves = 8704 B
#define STAGE_BYTES 47616
#define GEMM_SMEM (2 * STAGE_BYTES)                // 95232

extern __shared__ char smem_raw[];

__global__ __launch_bounds__(256, 2)
void gemm_mma_kernel(const float* __restrict__ A32,
                     const __half* __restrict__ Ahi,
                     const __half* __restrict__ Alo,
                     const __half* __restrict__ Bhi,
                     float* __restrict__ C_out, int M,
                     const float* __restrict__ att_src,
                     const float* __restrict__ att_dst,
                     float* __restrict__ asrc, float* __restrict__ adst,
                     int H, int Ch) {
    const int tid = threadIdx.x;
    const int lane = tid & 31;
    const int wid = tid >> 5;
    const int m0 = blockIdx.y * 128;
    const int n0 = blockIdx.x * 128;
    const int m_base = (wid >> 2) * 64;
    const int warp_n = wid & 3;
    const int n_base = warp_n * 32;

    uint32_t smem_u32 = (uint32_t)__cvta_generic_to_shared(smem_raw);
    const bool a_is_fp32 = (A32 != nullptr);

    const int arow0 = tid >> 2, acol0 = (tid & 3) * 8;     // fp16 A path
    const int brow0 = tid >> 4, bcol0 = (tid & 15) * 8;

    float acc[4][4][4];
    #pragma unroll
    for (int i = 0; i < 4; i++)
        #pragma unroll
        for (int j = 0; j < 4; j++)
            #pragma unroll
            for (int k = 0; k < 4; k++) acc[i][j][k] = 0.f;

    const int NIT = D / 32;

    auto load_stage = [&](int it, int s) {
        int k0 = it * 32;
        uint32_t base = smem_u32 + s * STAGE_BYTES;
        if (a_is_fp32) {
            // A: 128x32 fp32 = 1024 x 16B chunks, 4 per thread
            #pragma unroll
            for (int c = 0; c < 4; c++) {
                int ch = tid + c * 256;
                int row = ch >> 3, c4 = ch & 7;
                int gr = m0 + row;
                int ok = (gr < M) ? 16 : 0;
                cpasync16(base + ST_A32 + (uint32_t)(row * 144 + c4 * 16),
                          A32 + (size_t)gr * D + k0 + c4 * 4, ok);
            }
        } else {
            #pragma unroll
            for (int c = 0; c < 2; c++) {
                int row = arow0 + c * 64;
                int gr = m0 + row;
                int ok = (gr < M) ? 16 : 0;
                size_t goff = (size_t)gr * D + k0 + acol0;
                uint32_t soff = (uint32_t)(row * LDA_S + acol0) * 2;
                cpasync16(base + ST_AHI + soff, Ahi + goff, ok);
                cpasync16(base + ST_ALO + soff, Alo + goff, ok);
            }
        }
        #pragma unroll
        for (int c = 0; c < 2; c++) {
            int row = brow0 + c * 16;
            size_t goff = (size_t)(k0 + row) * D + n0 + bcol0;
            uint32_t soff = (uint32_t)(row * LDB_S + bcol0) * 2;
            cpasync16(base + ST_B + soff, Bhi + goff, 16);
        }
        cp_commit();
    };

    load_stage(0, 0);

    for (int it = 0; it < NIT; it++) {
        if (it + 1 < NIT) {
            load_stage(it + 1, (it + 1) & 1);
            cp_wait<1>();
        } else {
            cp_wait<0>();
        }
        __syncthreads();

        char* stg_gen = smem_raw + (it & 1) * STAGE_BYTES;
        if (a_is_fp32) {
            // convert 128x32 fp32 -> hi/lo fp16 (16 floats per thread)
            const float* a32 = (const float*)(stg_gen + ST_A32);
            __half2* ah = (__half2*)(stg_gen + ST_AHI);
            __half2* al = (__half2*)(stg_gen + ST_ALO);
            int r = tid >> 1, cb = (tid & 1) * 16;
            #pragma unroll
            for (int j = 0; j < 8; j++) {
                float2 v = *(const float2*)&a32[r * 36 + cb + 2 * j];
                __half h0 = __float2half_rn(v.x);
                __half h1 = __float2half_rn(v.y);
                __half2 hp; hp.x = h0; hp.y = h1;
                __half2 lp;
                lp.x = __float2half_rn(v.x - __half2float(h0));
                lp.y = __float2half_rn(v.y - __half2float(h1));
                int o = (r * LDA_S + cb + 2 * j) >> 1;   // half2 index
                ah[o] = hp;
                al[o] = lp;
            }
            __syncthreads();
        }

        uint32_t stg = smem_u32 + (it & 1) * STAGE_BYTES;
        #pragma unroll
        for (int kk = 0; kk < 2; kk++) {
            int kof = kk * 16;
            uint32_t bhi[4][2];
            #pragma unroll
            for (int p = 0; p < 2; p++) {
                uint32_t off = (uint32_t)((kof + (lane & 7) + 8 * ((lane >> 3) & 1)) * LDB_S
                                          + n_base + p * 16 + 8 * (lane >> 4)) * 2;
                uint32_t r[4];
                ldsm4t(r, stg + ST_B + off);
                bhi[p * 2][0] = r[0]; bhi[p * 2][1] = r[1];
                bhi[p * 2 + 1][0] = r[2]; bhi[p * 2 + 1][1] = r[3];
            }
            #pragma unroll
            for (int mh = 0; mh < 2; mh++) {
                uint32_t ahi[2][4], alo[2][4];
                #pragma unroll
                for (int q = 0; q < 2; q++) {
                    int mt = mh * 2 + q;
                    uint32_t off = (uint32_t)((m_base + mt * 16 + (lane & 15)) * LDA_S
                                              + kof + 8 * (lane >> 4)) * 2;
                    ldsm4(ahi[q], stg + ST_AHI + off);
                    ldsm4(alo[q], stg + ST_ALO + off);
                }
                #pragma unroll
                for (int q = 0; q < 2; q++)
                    #pragma unroll
                    for (int nt = 0; nt < 4; nt++) {
                        float* a = acc[mh * 2 + q][nt];
                        mma16816(a, ahi[q], bhi[nt]);
                        mma16816(a, alo[q], bhi[nt]);
                    }
            }
        }
        __syncthreads();
    }

    // ---- epilogue: store C ----
    const int gid = lane >> 2, t4 = lane & 3;
    #pragma unroll
    for (int mt = 0; mt < 4; mt++) {
        int r0 = m0 + m_base + mt * 16 + gid;
        int r1 = r0 + 8;
        #pragma unroll
        for (int nt = 0; nt < 4; nt++) {
            int col = n0 + n_base + nt * 8 + t4 * 2;
            if (r0 < M) *(float2*)&C_out[(size_t)r0 * D + col] = make_float2(acc[mt][nt][0], acc[mt][nt][1]);
            if (r1 < M) *(float2*)&C_out[(size_t)r1 * D + col] = make_float2(acc[mt][nt][2], acc[mt][nt][3]);
        }
    }

    // ---- epilogue: attention dots, smem cross-warp reduce, plain stores ----
    const int h_t = (n0 + n_base) / Ch;
    float av_s[8], av_d[8];
    #pragma unroll
    for (int nt = 0; nt < 4; nt++) {
        int ci = (n0 + n_base + nt * 8 + t4 * 2) % Ch;
        av_s[nt * 2]     = att_src[h_t * Ch + ci];
        av_s[nt * 2 + 1] = att_src[h_t * Ch + ci + 1];
        av_d[nt * 2]     = att_dst[h_t * Ch + ci];
        av_d[nt * 2 + 1] = att_dst[h_t * Ch + ci + 1];
    }
    float* s_arr = (float*)smem_raw;
    float* d_arr = s_arr + 512;
    #pragma unroll
    for (int mt = 0; mt < 4; mt++) {
        float s0 = 0.f, d0 = 0.f, s1 = 0.f, d1 = 0.f;
        #pragma unroll
        for (int nt = 0; nt < 4; nt++) {
            s0 += acc[mt][nt][0] * av_s[nt * 2] + acc[mt][nt][1] * av_s[nt * 2 + 1];
            d0 += acc[mt][nt][0] * av_d[nt * 2] + acc[mt][nt][1] * av_d[nt * 2 + 1];
            s1 += acc[mt][nt][2] * av_s[nt * 2] + acc[mt][nt][3] * av_s[nt * 2 + 1];
            d1 += acc[mt][nt][2] * av_d[nt * 2] + acc[mt][nt][3] * av_d[nt * 2 + 1];
        }
        #pragma unroll
        for (int o = 1; o < 4; o <<= 1) {
            s0 += __shfl_xor_sync(0xffffffffu, s0, o);
            d0 += __shfl_xor_sync(0xffffffffu, d0, o);
            s1 += __shfl_xor_sync(0xffffffffu, s1, o);
            d1 += __shfl_xor_sync(0xffffffffu, d1, o);
        }
        if (t4 == 0) {
            int rl0 = m_base + mt * 16 + gid;
            int rl1 = rl0 + 8;
            s_arr[warp_n * 128 + rl0] = s0;
            d_arr[warp_n * 128 + rl0] = d0;
            s_arr[warp_n * 128 + rl1] = s1;
            d_arr[warp_n * 128 + rl1] = d1;
        }
    }
    __syncthreads();
    const int nh = 128 / Ch;
    const int wph = Ch / 32;
    if (tid < 128 * nh) {
        int row = tid & 127;
        int hl = tid >> 7;
        float ssum = 0.f, dsum = 0.f;
        for (int w = hl * wph; w < hl * wph + wph; w++) {
            ssum += s_arr[w * 128 + row];
            dsum += d_arr[w * 128 + row];
        }
        int gr = m0 + row;
        if (gr < M) {
            int gh = n0 / Ch + hl;
            asrc[gr * H + gh] = ssum;
            adst[gr * H + gh] = dsum;
        }
    }
}

// ---------------- fused score+softmax+aggregate (+CE loss & finalize, mode 1) ---
__global__ __launch_bounds__(128)
void agg_kernel(const float* __restrict__ xp,
                const float* __restrict__ asrc, const float* __restrict__ adst,
                const float* __restrict__ bias, float* __restrict__ out,
                __half* __restrict__ out_hi, __half* __restrict__ out_lo,
                const int* __restrict__ ei,
                const int* __restrict__ y, const int* __restrict__ mask,
                float* __restrict__ out_final, int write_loss,
                int E, int H, int lgH, int C, int mode) {
    __shared__ float sh_alpha[CHUNK * H1v];
    __shared__ int   sh_src[CHUNK];
    __shared__ float sh_m[H1v], sh_s[H1v], sh_ad[H1v];
    __shared__ float sh_red[512];
    __shared__ float sm4[4], ss4[4];
    int n = blockIdx.x;
    int tid = threadIdx.x;
    int w = tid >> 5, lane = tid & 31;
    int beg = g_rowstart[n], end = beg + g_deg[n];

    for (int h = w; h < H; h += 4) {
        float ad = adst[n * H + h];
        float m = -1e30f;
        for (int i = beg + lane; i < end; i += 32) {
            int eid = g_csr[i];
            int s = (eid < E) ? ei[eid] : (eid - E);
            float v = asrc[s * H + h] + ad;
            v = v > 0.f ? v : 0.2f * v;
            m = fmaxf(m, v);
        }
        m = warp_max(m);
        float su = 0.f;
        for (int i = beg + lane; i < end; i += 32) {
            int eid = g_csr[i];
            int s = (eid < E) ? ei[eid] : (eid - E);
            float v = asrc[s * H + h] + ad;
            v = v > 0.f ? v : 0.2f * v;
            su += expf(v - m);
        }
        su = warp_sum(su);
        if (lane == 0) { sh_m[h] = m; sh_s[h] = su + 1e-16f; sh_ad[h] = ad; }
    }
    __syncthreads();

    const int p1 = tid + 128;
    const int hh0 = tid / (C / 2);
    const int hh1 = p1 / (C / 2);
    float2 acc0 = make_float2(0.f, 0.f), acc1 = make_float2(0.f, 0.f);
    for (int cs = beg; cs < end; cs += CHUNK) {
        int cn = min(CHUNK, end - cs);
        if (tid < cn) {
            int eid = g_csr[cs + tid];
            sh_src[tid] = (eid < E) ? ei[eid] : (eid - E);
        }
        __syncthreads();
        for (int idx = tid; idx < (cn << lgH); idx += 128) {
            int i = idx >> lgH, h = idx & (H - 1);
            float v = asrc[sh_src[i] * H + h] + sh_ad[h];
            v = v > 0.f ? v : 0.2f * v;
            sh_alpha[(i << lgH) + h] = expf(v - sh_m[h]) / sh_s[h];
        }
        __syncthreads();
        for (int i = 0; i < cn; i++) {
            const float2* row = (const float2*)(xp + (size_t)sh_src[i] * D);
            float a0 = sh_alpha[(i << lgH) + hh0];
            float a1 = sh_alpha[(i << lgH) + hh1];
            float2 r0 = row[tid], r1 = row[p1];
            acc0.x += a0 * r0.x; acc0.y += a0 * r0.y;
            acc1.x += a1 * r1.x; acc1.y += a1 * r1.y;
        }
        __syncthreads();
    }

    if (mode == 0) {
        float v0 = acc0.x + bias[tid * 2];
        float v1 = acc0.y + bias[tid * 2 + 1];
        float v2 = acc1.x + bias[p1 * 2];
        float v3 = acc1.y + bias[p1 * 2 + 1];
        v0 = v0 > 0.f ? v0 : expm1f(v0);
        v1 = v1 > 0.f ? v1 : expm1f(v1);
        v2 = v2 > 0.f ? v2 : expm1f(v2);
        v3 = v3 > 0.f ? v3 : expm1f(v3);
        __half h0 = __float2half_rn(v0), h1 = __float2half_rn(v1);
        __half h2 = __float2half_rn(v2), h3 = __float2half_rn(v3);
        __half2 hp0; hp0.x = h0; hp0.y = h1;
        __half2 hp1; hp1.x = h2; hp1.y = h3;
        __half2 lp0, lp1;
        lp0.x = __float2half_rn(v0 - __half2float(h0));
        lp0.y = __float2half_rn(v1 - __half2float(h1));
        lp1.x = __float2half_rn(v2 - __half2float(h2));
        lp1.y = __float2half_rn(v3 - __half2float(h3));
        __half2* oh = (__half2*)(out_hi + (size_t)n * D);
        __half2* ol = (__half2*)(out_lo + (size_t)n * D);
        oh[tid] = hp0; oh[p1] = hp1;
        ol[tid] = lp0; ol[p1] = lp1;
    } else {
        sh_red[tid * 2]     = acc0.x;
        sh_red[tid * 2 + 1] = acc0.y;
        sh_red[p1 * 2]      = acc1.x;
        sh_red[p1 * 2 + 1]  = acc1.y;
        __syncthreads();
        float s = 0.f;
        for (int h = 0; h < H; h++) s += sh_red[h * C + tid];
        float logit = s / (float)H + bias[tid];
        out[(size_t)n * C + tid] = logit;
        __syncthreads();
        sh_red[tid] = logit;
        float mx = warp_max(logit);
        if (lane == 0) sm4[w] = mx;
        __syncthreads();
        mx = fmaxf(fmaxf(sm4[0], sm4[1]), fmaxf(sm4[2], sm4[3]));
        float se = warp_sum(expf(logit - mx));
        if (lane == 0) ss4[w] = se;
        __syncthreads();
        if (tid == 0) {
            bool mv = g_mask_byte ? (((const unsigned char*)mask)[n] != 0) : (mask[n] != 0);
            if (mv) {
                float lse = mx + logf(ss4[0] + ss4[1] + ss4[2] + ss4[3]);
                atomicAdd(&g_accum[0], lse - sh_red[y[n]]);
                atomicAdd(&g_accum[1], 1.f);
            }
            // finalize: last block writes the mean loss
            __threadfence();
            if (atomicAdd(&g_done, 1u) == gridDim.x - 1) {
                if (write_loss) {
                    float a = atomicAdd(&g_accum[0], 0.f);
                    float b = atomicAdd(&g_accum[1], 0.f);
                    out_final[0] = a / b;
                }
            }
        }
    }
}

// ---------------- launch --------------------------------------------------------
extern "C" void kernel_launch(void* const* d_in, const int* in_sizes, int n_in,
                              void* d_out, int out_size) {
    const float* x       = (const float*)d_in[0];
    const int*   ei      = (const int*)d_in[1];
    const int*   y       = (const int*)d_in[2];
    const int*   mask    = (const int*)d_in[3];
    const float* W1      = (const float*)d_in[4];
    const float* att_s1  = (const float*)d_in[5];
    const float* att_d1  = (const float*)d_in[6];
    const float* b1      = (const float*)d_in[7];
    const float* W2      = (const float*)d_in[8];
    const float* att_s2  = (const float*)d_in[9];
    const float* att_d2  = (const float*)d_in[10];
    const float* b2      = (const float*)d_in[11];
    float* out_f = (float*)d_out;

    int N = in_sizes[0] / D;        // 20000
    int E = in_sizes[1] / 2;        // 100000
    int EP = E + N;

    float *p_xp, *p_asrc, *p_adst;
    __half *p_Ahi, *p_Alo, *p_Bhi, *p_B2hi;
    cudaGetSymbolAddress((void**)&p_xp, g_xp);
    cudaGetSymbolAddress((void**)&p_asrc, g_asrc);
    cudaGetSymbolAddress((void**)&p_adst, g_adst);
    cudaGetSymbolAddress((void**)&p_Ahi, g_Ahi);
    cudaGetSymbolAddress((void**)&p_Alo, g_Alo);
    cudaGetSymbolAddress((void**)&p_Bhi, g_Bhi);
    cudaGetSymbolAddress((void**)&p_B2hi, g_B2hi);

    cudaFuncSetAttribute(gemm_mma_kernel,
                         cudaFuncAttributeMaxDynamicSharedMemorySize, GEMM_SMEM);

    int has_loss = (out_size == N * C2v + 1) ? 1 : 0;
    float* p_logits = out_f + has_loss;

    // --- init + W splits + CSR (one grid-synced kernel; 469 blocks co-resident) ---
    mega_kernel<<<(EP + 255) / 256, 256>>>(ei, (const unsigned int*)mask,
                                           W1, W2, p_Bhi, p_B2hi, E, N);

    dim3 ggrid(D / 128, (N + 127) / 128);

    // --- layer 1 (A = fp32 x, converted in-kernel) ---
    gemm_mma_kernel<<<ggrid, 256, GEMM_SMEM>>>(x, p_Ahi, p_Alo, p_Bhi, p_xp, N,
                                               att_s1, att_d1, p_asrc, p_adst, H1v, C1v);
    agg_kernel<<<N, 128>>>(p_xp, p_asrc, p_adst, b1, nullptr, p_Ahi, p_Alo,
                           ei, nullptr, nullptr, nullptr, 0, E, H1v, 3, C1v, 0);

    // --- layer 2 (A = fp16 hi/lo from agg1; agg2 fuses CE loss + finalize) ---
    gemm_mma_kernel<<<ggrid, 256, GEMM_SMEM>>>(nullptr, p_Ahi, p_Alo, p_B2hi, p_xp, N,
                                               att_s2, att_d2, p_asrc, p_adst, H2v, C2v);
    agg_kernel<<<N, 128>>>(p_xp, p_asrc, p_adst, b2, p_logits, nullptr, nullptr,
                           ei, y, mask, out_f, has_loss, E, H2v, 2, C2v, 1);
}

// round 17
// speedup vs baseline: 1.0490x; 1.0490x over previous
#include <cuda_runtime.h>
#include <cuda_fp16.h>
#include <math.h>
#include <stdint.h>

// Problem constants
#define D      512
#define NNODES 20000
#define NEDGES 100000
#define EPRIME (NEDGES + NNODES)
#define H1v    8
#define C1v    64
#define H2v    4
#define C2v    128
#define CHUNK  128

// ---------------- scratch (device globals; no allocation allowed) -------------
__device__ float g_xp[(size_t)NNODES * D];
__device__ float g_asrc[(size_t)NNODES * H1v];
__device__ float g_adst[(size_t)NNODES * H1v];
__device__ int   g_deg[NNODES];
__device__ int   g_rowstart[NNODES];
__device__ int   g_cursor[NNODES];
__device__ int   g_csr[EPRIME];
__device__ float g_accum[2];
__device__ int   g_mask_byte;
__device__ int   g_total;
__device__ unsigned g_bar;
__device__ unsigned g_exit;
__device__ unsigned g_done;
__device__ __half g_Ahi[(size_t)NNODES * D];
__device__ __half g_Alo[(size_t)NNODES * D];
__device__ __half g_Bhi[(size_t)D * D];
__device__ __half g_B2hi[(size_t)D * D];

// ---------------- helpers ----------------------------------------------------
__device__ __forceinline__ float warp_max(float v) {
    #pragma unroll
    for (int o = 16; o; o >>= 1) v = fmaxf(v, __shfl_xor_sync(0xffffffffu, v, o));
    return v;
}
__device__ __forceinline__ float warp_sum(float v) {
    #pragma unroll
    for (int o = 16; o; o >>= 1) v += __shfl_xor_sync(0xffffffffu, v, o);
    return v;
}

__device__ __forceinline__ void mma16816(float* c, const uint32_t* a, const uint32_t* b) {
    asm volatile(
        "mma.sync.aligned.m16n8k16.row.col.f32.f16.f16.f32 "
        "{%0,%1,%2,%3}, {%4,%5,%6,%7}, {%8,%9}, {%0,%1,%2,%3};\n"
        : "+f"(c[0]), "+f"(c[1]), "+f"(c[2]), "+f"(c[3])
        : "r"(a[0]), "r"(a[1]), "r"(a[2]), "r"(a[3]), "r"(b[0]), "r"(b[1]));
}
__device__ __forceinline__ void ldsm4(uint32_t* r, uint32_t addr) {
    asm volatile("ldmatrix.sync.aligned.m8n8.x4.shared.b16 {%0,%1,%2,%3}, [%4];\n"
        : "=r"(r[0]), "=r"(r[1]), "=r"(r[2]), "=r"(r[3]) : "r"(addr));
}
__device__ __forceinline__ void ldsm4t(uint32_t* r, uint32_t addr) {
    asm volatile("ldmatrix.sync.aligned.m8n8.x4.trans.shared.b16 {%0,%1,%2,%3}, [%4];\n"
        : "=r"(r[0]), "=r"(r[1]), "=r"(r[2]), "=r"(r[3]) : "r"(addr));
}
__device__ __forceinline__ void cpasync16(uint32_t dst, const void* src, int srcsize) {
    asm volatile("cp.async.cg.shared.global [%0], [%1], 16, %2;\n"
        :: "r"(dst), "l"(src), "r"(srcsize));
}
__device__ __forceinline__ void cp_commit() { asm volatile("cp.async.commit_group;\n"); }
template<int NW> __device__ __forceinline__ void cp_wait() {
    asm volatile("cp.async.wait_group %0;\n" :: "n"(NW));
}

// ---------------- mega kernel: init + x/W splits + CSR build (grid-synced) -----
__device__ __forceinline__ void grid_sync_phase(unsigned target) {
    __syncthreads();
    if (threadIdx.x == 0) {
        __threadfence();
        atomicAdd(&g_bar, 1u);
        while (atomicAdd(&g_bar, 0u) < target) { }
        __threadfence();
    }
    __syncthreads();
}

__global__ __launch_bounds__(256)
void mega_kernel(const int* __restrict__ ei, const unsigned int* __restrict__ m,
                 const float* __restrict__ x,
                 const float* __restrict__ W1, const float* __restrict__ W2,
                 __half* __restrict__ Ahi, __half* __restrict__ Alo,
                 __half* __restrict__ B1hi, __half* __restrict__ B2hi,
                 int nx, int E, int N) {
    const unsigned nb = gridDim.x;
    int gi = blockIdx.x * blockDim.x + threadIdx.x;
    int stride = nb * blockDim.x;
    const int nw = D * D;
    // ---- phase 0: zero state + split x to fp16 hi/lo + split W1/W2 ----
    if (gi < N) g_deg[gi] = 0;
    if (gi == 0) {
        g_accum[0] = 0.f; g_accum[1] = 0.f;
        g_total = 0; g_mask_byte = 0; g_done = 0u;
    }
    for (int i = gi; i < nx; i += stride) {
        float v = x[i];
        __half h = __float2half_rn(v);
        Ahi[i] = h;
        Alo[i] = __float2half_rn(v - __half2float(h));
    }
    for (int i = gi; i < 2 * nw; i += stride) {
        if (i < nw) B1hi[i] = __float2half_rn(W1[i]);
        else        B2hi[i - nw] = __float2half_rn(W2[i - nw]);
    }
    grid_sync_phase(nb);
    // ---- phase 1: histogram + mask dtype detect ----
    if (gi < N / 4) {
        unsigned v = m[gi];
        if (v != 0u && v != 1u && v != 0x3F800000u) atomicOr(&g_mask_byte, 1);
    }
    if (gi < E + N) {
        int d = (gi < E) ? ei[E + gi] : (gi - E);
        atomicAdd(&g_deg[d], 1);
    }
    grid_sync_phase(2 * nb);
    // ---- phase 2: segment offsets ----
    if (gi < N) {
        int base = atomicAdd(&g_total, g_deg[gi]);
        g_rowstart[gi] = base;
        g_cursor[gi] = base;
    }
    grid_sync_phase(3 * nb);
    // ---- phase 3: scatter ----
    if (gi < E + N) {
        int d = (gi < E) ? ei[E + gi] : (gi - E);
        int pos = atomicAdd(&g_cursor[d], 1);
        g_csr[pos] = gi;
    }
    // ---- exit: last block resets barrier state for next graph replay ----
    __syncthreads();
    if (threadIdx.x == 0) {
        __threadfence();
        if (atomicAdd(&g_exit, 1u) == nb - 1) {
            atomicExch(&g_bar, 0u);
            atomicExch(&g_exit, 0u);
        }
    }
}

// ---------------- tensor-core GEMM + fused attention (atomic-free) --------------
// fp16 hi/lo A, fp16 B. KC=64 per stage -> 8 iterations, 2 syncs each.
#define KC 64
#define LDA_S 72      // 64 + 8 pad (halves); row stride 144B
#define LDB_S 136     // 128 + 8 pad (halves)
#define ST_AHI 0
#define ST_ALO 18432                               // 128*72*2
#define ST_B   36864                               // + 18432
#define STAGE_BYTES 54272                          // + 64*136*2
#define GEMM_SMEM (2 * STAGE_BYTES)                // 108544

extern __shared__ char smem_raw[];

__global__ __launch_bounds__(256, 2)
void gemm_mma_kernel(const __half* __restrict__ Ahi,
                     const __half* __restrict__ Alo,
                     const __half* __restrict__ Bhi,
                     float* __restrict__ C_out, int M,
                     const float* __restrict__ att_src,
                     const float* __restrict__ att_dst,
                     float* __restrict__ asrc, float* __restrict__ adst,
                     int H, int Ch) {
    const int tid = threadIdx.x;
    const int lane = tid & 31;
    const int wid = tid >> 5;
    const int m0 = blockIdx.y * 128;
    const int n0 = blockIdx.x * 128;
    const int m_base = (wid >> 2) * 64;
    const int warp_n = wid & 3;
    const int n_base = warp_n * 32;

    uint32_t smem_u32 = (uint32_t)__cvta_generic_to_shared(smem_raw);

    float acc[4][4][4];
    #pragma unroll
    for (int i = 0; i < 4; i++)
        #pragma unroll
        for (int j = 0; j < 4; j++)
            #pragma unroll
            for (int k = 0; k < 4; k++) acc[i][j][k] = 0.f;

    const int NIT = D / KC;   // 8

    auto load_stage = [&](int it, int s) {
        int k0 = it * KC;
        uint32_t base = smem_u32 + s * STAGE_BYTES;
        // A: 128 rows x 64 halves, hi+lo: 4 chunks each per thread
        #pragma unroll
        for (int c = 0; c < 4; c++) {
            int ch = tid + c * 256;             // 0..1023
            int row = ch >> 3, c16 = ch & 7;    // 8 chunks per row
            int gr = m0 + row;
            int ok = (gr < M) ? 16 : 0;
            size_t goff = (size_t)gr * D + k0 + c16 * 8;
            uint32_t soff = (uint32_t)(row * LDA_S + c16 * 8) * 2;
            cpasync16(base + ST_AHI + soff, Ahi + goff, ok);
            cpasync16(base + ST_ALO + soff, Alo + goff, ok);
        }
        // B: 64 rows x 128 halves: 4 chunks per thread
        #pragma unroll
        for (int c = 0; c < 4; c++) {
            int ch = tid + c * 256;             // 0..1023
            int row = ch >> 4, c16 = ch & 15;   // 16 chunks per row
            size_t goff = (size_t)(k0 + row) * D + n0 + c16 * 8;
            uint32_t soff = (uint32_t)(row * LDB_S + c16 * 8) * 2;
            cpasync16(base + ST_B + soff, Bhi + goff, 16);
        }
        cp_commit();
    };

    load_stage(0, 0);

    for (int it = 0; it < NIT; it++) {
        if (it + 1 < NIT) {
            load_stage(it + 1, (it + 1) & 1);
            cp_wait<1>();
        } else {
            cp_wait<0>();
        }
        __syncthreads();

        uint32_t stg = smem_u32 + (it & 1) * STAGE_BYTES;
        #pragma unroll
        for (int kk = 0; kk < 4; kk++) {
            int kof = kk * 16;
            uint32_t bhi[4][2];
            #pragma unroll
            for (int p = 0; p < 2; p++) {
                uint32_t off = (uint32_t)((kof + (lane & 7) + 8 * ((lane >> 3) & 1)) * LDB_S
                                          + n_base + p * 16 + 8 * (lane >> 4)) * 2;
                uint32_t r[4];
                ldsm4t(r, stg + ST_B + off);
                bhi[p * 2][0] = r[0]; bhi[p * 2][1] = r[1];
                bhi[p * 2 + 1][0] = r[2]; bhi[p * 2 + 1][1] = r[3];
            }
            #pragma unroll
            for (int mh = 0; mh < 2; mh++) {
                uint32_t ahi[2][4], alo[2][4];
                #pragma unroll
                for (int q = 0; q < 2; q++) {
                    int mt = mh * 2 + q;
                    uint32_t off = (uint32_t)((m_base + mt * 16 + (lane & 15)) * LDA_S
                                              + kof + 8 * (lane >> 4)) * 2;
                    ldsm4(ahi[q], stg + ST_AHI + off);
                    ldsm4(alo[q], stg + ST_ALO + off);
                }
                #pragma unroll
                for (int q = 0; q < 2; q++)
                    #pragma unroll
                    for (int nt = 0; nt < 4; nt++) {
                        float* a = acc[mh * 2 + q][nt];
                        mma16816(a, ahi[q], bhi[nt]);
                        mma16816(a, alo[q], bhi[nt]);
                    }
            }
        }
        __syncthreads();
    }

    // ---- epilogue: store C ----
    const int gid = lane >> 2, t4 = lane & 3;
    #pragma unroll
    for (int mt = 0; mt < 4; mt++) {
        int r0 = m0 + m_base + mt * 16 + gid;
        int r1 = r0 + 8;
        #pragma unroll
        for (int nt = 0; nt < 4; nt++) {
            int col = n0 + n_base + nt * 8 + t4 * 2;
            if (r0 < M) *(float2*)&C_out[(size_t)r0 * D + col] = make_float2(acc[mt][nt][0], acc[mt][nt][1]);
            if (r1 < M) *(float2*)&C_out[(size_t)r1 * D + col] = make_float2(acc[mt][nt][2], acc[mt][nt][3]);
        }
    }

    // ---- epilogue: attention dots, smem cross-warp reduce, plain stores ----
    const int h_t = (n0 + n_base) / Ch;
    float av_s[8], av_d[8];
    #pragma unroll
    for (int nt = 0; nt < 4; nt++) {
        int ci = (n0 + n_base + nt * 8 + t4 * 2) % Ch;
        av_s[nt * 2]     = att_src[h_t * Ch + ci];
        av_s[nt * 2 + 1] = att_src[h_t * Ch + ci + 1];
        av_d[nt * 2]     = att_dst[h_t * Ch + ci];
        av_d[nt * 2 + 1] = att_dst[h_t * Ch + ci + 1];
    }
    float* s_arr = (float*)smem_raw;
    float* d_arr = s_arr + 512;
    #pragma unroll
    for (int mt = 0; mt < 4; mt++) {
        float s0 = 0.f, d0 = 0.f, s1 = 0.f, d1 = 0.f;
        #pragma unroll
        for (int nt = 0; nt < 4; nt++) {
            s0 += acc[mt][nt][0] * av_s[nt * 2] + acc[mt][nt][1] * av_s[nt * 2 + 1];
            d0 += acc[mt][nt][0] * av_d[nt * 2] + acc[mt][nt][1] * av_d[nt * 2 + 1];
            s1 += acc[mt][nt][2] * av_s[nt * 2] + acc[mt][nt][3] * av_s[nt * 2 + 1];
            d1 += acc[mt][nt][2] * av_d[nt * 2] + acc[mt][nt][3] * av_d[nt * 2 + 1];
        }
        #pragma unroll
        for (int o = 1; o < 4; o <<= 1) {
            s0 += __shfl_xor_sync(0xffffffffu, s0, o);
            d0 += __shfl_xor_sync(0xffffffffu, d0, o);
            s1 += __shfl_xor_sync(0xffffffffu, s1, o);
            d1 += __shfl_xor_sync(0xffffffffu, d1, o);
        }
        if (t4 == 0) {
            int rl0 = m_base + mt * 16 + gid;
            int rl1 = rl0 + 8;
            s_arr[warp_n * 128 + rl0] = s0;
            d_arr[warp_n * 128 + rl0] = d0;
            s_arr[warp_n * 128 + rl1] = s1;
            d_arr[warp_n * 128 + rl1] = d1;
        }
    }
    __syncthreads();
    const int nh = 128 / Ch;
    const int wph = Ch / 32;
    if (tid < 128 * nh) {
        int row = tid & 127;
        int hl = tid >> 7;
        float ssum = 0.f, dsum = 0.f;
        for (int w = hl * wph; w < hl * wph + wph; w++) {
            ssum += s_arr[w * 128 + row];
            dsum += d_arr[w * 128 + row];
        }
        int gr = m0 + row;
        if (gr < M) {
            int gh = n0 / Ch + hl;
            asrc[gr * H + gh] = ssum;
            adst[gr * H + gh] = dsum;
        }
    }
}

// ---------------- fused score+softmax+aggregate (+CE loss & finalize, mode 1) ---
__global__ __launch_bounds__(128)
void agg_kernel(const float* __restrict__ xp,
                const float* __restrict__ asrc, const float* __restrict__ adst,
                const float* __restrict__ bias, float* __restrict__ out,
                __half* __restrict__ out_hi, __half* __restrict__ out_lo,
                const int* __restrict__ ei,
                const int* __restrict__ y, const int* __restrict__ mask,
                float* __restrict__ out_final, int write_loss,
                int E, int H, int lgH, int C, int mode) {
    __shared__ float sh_alpha[CHUNK * H1v];
    __shared__ int   sh_src[CHUNK];
    __shared__ float sh_m[H1v], sh_s[H1v], sh_ad[H1v];
    __shared__ float sh_red[512];
    __shared__ float sm4[4], ss4[4];
    int n = blockIdx.x;
    int tid = threadIdx.x;
    int w = tid >> 5, lane = tid & 31;
    int beg = g_rowstart[n], end = beg + g_deg[n];

    for (int h = w; h < H; h += 4) {
        float ad = adst[n * H + h];
        float m = -1e30f;
        for (int i = beg + lane; i < end; i += 32) {
            int eid = g_csr[i];
            int s = (eid < E) ? ei[eid] : (eid - E);
            float v = asrc[s * H + h] + ad;
            v = v > 0.f ? v : 0.2f * v;
            m = fmaxf(m, v);
        }
        m = warp_max(m);
        float su = 0.f;
        for (int i = beg + lane; i < end; i += 32) {
            int eid = g_csr[i];
            int s = (eid < E) ? ei[eid] : (eid - E);
            float v = asrc[s * H + h] + ad;
            v = v > 0.f ? v : 0.2f * v;
            su += expf(v - m);
        }
        su = warp_sum(su);
        if (lane == 0) { sh_m[h] = m; sh_s[h] = su + 1e-16f; sh_ad[h] = ad; }
    }
    __syncthreads();

    const int p1 = tid + 128;
    const int hh0 = tid / (C / 2);
    const int hh1 = p1 / (C / 2);
    float2 acc0 = make_float2(0.f, 0.f), acc1 = make_float2(0.f, 0.f);
    for (int cs = beg; cs < end; cs += CHUNK) {
        int cn = min(CHUNK, end - cs);
        if (tid < cn) {
            int eid = g_csr[cs + tid];
            sh_src[tid] = (eid < E) ? ei[eid] : (eid - E);
        }
        __syncthreads();
        for (int idx = tid; idx < (cn << lgH); idx += 128) {
            int i = idx >> lgH, h = idx & (H - 1);
            float v = asrc[sh_src[i] * H + h] + sh_ad[h];
            v = v > 0.f ? v : 0.2f * v;
            sh_alpha[(i << lgH) + h] = expf(v - sh_m[h]) / sh_s[h];
        }
        __syncthreads();
        for (int i = 0; i < cn; i++) {
            const float2* row = (const float2*)(xp + (size_t)sh_src[i] * D);
            float a0 = sh_alpha[(i << lgH) + hh0];
            float a1 = sh_alpha[(i << lgH) + hh1];
            float2 r0 = row[tid], r1 = row[p1];
            acc0.x += a0 * r0.x; acc0.y += a0 * r0.y;
            acc1.x += a1 * r1.x; acc1.y += a1 * r1.y;
        }
        __syncthreads();
    }

    if (mode == 0) {
        float v0 = acc0.x + bias[tid * 2];
        float v1 = acc0.y + bias[tid * 2 + 1];
        float v2 = acc1.x + bias[p1 * 2];
        float v3 = acc1.y + bias[p1 * 2 + 1];
        v0 = v0 > 0.f ? v0 : expm1f(v0);
        v1 = v1 > 0.f ? v1 : expm1f(v1);
        v2 = v2 > 0.f ? v2 : expm1f(v2);
        v3 = v3 > 0.f ? v3 : expm1f(v3);
        __half h0 = __float2half_rn(v0), h1 = __float2half_rn(v1);
        __half h2 = __float2half_rn(v2), h3 = __float2half_rn(v3);
        __half2 hp0; hp0.x = h0; hp0.y = h1;
        __half2 hp1; hp1.x = h2; hp1.y = h3;
        __half2 lp0, lp1;
        lp0.x = __float2half_rn(v0 - __half2float(h0));
        lp0.y = __float2half_rn(v1 - __half2float(h1));
        lp1.x = __float2half_rn(v2 - __half2float(h2));
        lp1.y = __float2half_rn(v3 - __half2float(h3));
        __half2* oh = (__half2*)(out_hi + (size_t)n * D);
        __half2* ol = (__half2*)(out_lo + (size_t)n * D);
        oh[tid] = hp0; oh[p1] = hp1;
        ol[tid] = lp0; ol[p1] = lp1;
    } else {
        sh_red[tid * 2]     = acc0.x;
        sh_red[tid * 2 + 1] = acc0.y;
        sh_red[p1 * 2]      = acc1.x;
        sh_red[p1 * 2 + 1]  = acc1.y;
        __syncthreads();
        float s = 0.f;
        for (int h = 0; h < H; h++) s += sh_red[h * C + tid];
        float logit = s / (float)H + bias[tid];
        out[(size_t)n * C + tid] = logit;
        __syncthreads();
        sh_red[tid] = logit;
        float mx = warp_max(logit);
        if (lane == 0) sm4[w] = mx;
        __syncthreads();
        mx = fmaxf(fmaxf(sm4[0], sm4[1]), fmaxf(sm4[2], sm4[3]));
        float se = warp_sum(expf(logit - mx));
        if (lane == 0) ss4[w] = se;
        __syncthreads();
        if (tid == 0) {
            bool mv = g_mask_byte ? (((const unsigned char*)mask)[n] != 0) : (mask[n] != 0);
            if (mv) {
                float lse = mx + logf(ss4[0] + ss4[1] + ss4[2] + ss4[3]);
                atomicAdd(&g_accum[0], lse - sh_red[y[n]]);
                atomicAdd(&g_accum[1], 1.f);
            }
            __threadfence();
            if (atomicAdd(&g_done, 1u) == gridDim.x - 1) {
                if (write_loss) {
                    float a = atomicAdd(&g_accum[0], 0.f);
                    float b = atomicAdd(&g_accum[1], 0.f);
                    out_final[0] = a / b;
                }
            }
        }
    }
}

// ---------------- launch --------------------------------------------------------
extern "C" void kernel_launch(void* const* d_in, const int* in_sizes, int n_in,
                              void* d_out, int out_size) {
    const float* x       = (const float*)d_in[0];
    const int*   ei      = (const int*)d_in[1];
    const int*   y       = (const int*)d_in[2];
    const int*   mask    = (const int*)d_in[3];
    const float* W1      = (const float*)d_in[4];
    const float* att_s1  = (const float*)d_in[5];
    const float* att_d1  = (const float*)d_in[6];
    const float* b1      = (const float*)d_in[7];
    const float* W2      = (const float*)d_in[8];
    const float* att_s2  = (const float*)d_in[9];
    const float* att_d2  = (const float*)d_in[10];
    const float* b2      = (const float*)d_in[11];
    float* out_f = (float*)d_out;

    int N = in_sizes[0] / D;        // 20000
    int E = in_sizes[1] / 2;        // 100000

    float *p_xp, *p_asrc, *p_adst;
    __half *p_Ahi, *p_Alo, *p_Bhi, *p_B2hi;
    cudaGetSymbolAddress((void**)&p_xp, g_xp);
    cudaGetSymbolAddress((void**)&p_asrc, g_asrc);
    cudaGetSymbolAddress((void**)&p_adst, g_adst);
    cudaGetSymbolAddress((void**)&p_Ahi, g_Ahi);
    cudaGetSymbolAddress((void**)&p_Alo, g_Alo);
    cudaGetSymbolAddress((void**)&p_Bhi, g_Bhi);
    cudaGetSymbolAddress((void**)&p_B2hi, g_B2hi);

    cudaFuncSetAttribute(gemm_mma_kernel,
                         cudaFuncAttributeMaxDynamicSharedMemorySize, GEMM_SMEM);

    int has_loss = (out_size == N * C2v + 1) ? 1 : 0;
    float* p_logits = out_f + has_loss;

    // --- init + x/W splits + CSR (one grid-synced kernel; 1184 blocks co-resident) ---
    mega_kernel<<<1184, 256>>>(ei, (const unsigned int*)mask, x, W1, W2,
                               p_Ahi, p_Alo, p_Bhi, p_B2hi, N * D, E, N);

    dim3 ggrid(D / 128, (N + 127) / 128);

    // --- layer 1 ---
    gemm_mma_kernel<<<ggrid, 256, GEMM_SMEM>>>(p_Ahi, p_Alo, p_Bhi, p_xp, N,
                                               att_s1, att_d1, p_asrc, p_adst, H1v, C1v);
    agg_kernel<<<N, 128>>>(p_xp, p_asrc, p_adst, b1, nullptr, p_Ahi, p_Alo,
                           ei, nullptr, nullptr, nullptr, 0, E, H1v, 3, C1v, 0);

    // --- layer 2 (agg2 fuses CE loss + finalize) ---
    gemm_mma_kernel<<<ggrid, 256, GEMM_SMEM>>>(p_Ahi, p_Alo, p_B2hi, p_xp, N,
                                               att_s2, att_d2, p_asrc, p_adst, H2v, C2v);
    agg_kernel<<<N, 128>>>(p_xp, p_asrc, p_adst, b2, p_logits, nullptr, nullptr,
                           ei, y, mask, out_f, has_loss, E, H2v, 2, C2v, 1);
}